// round 6
// baseline (speedup 1.0000x reference)
#include <cuda_runtime.h>

// FNNKernelTransform: per-edge MLP(4->128->128->1056) -> (32x33) kernel -> mat@v + bias
// Fused fp32 implementation with packed f32x2 FMA (Blackwell FFMA2).
//
// Strategy:
//   prep kernel : W3 [128,1056] -> W3p [128,1280] (each 33-col i-block zero-padded to 40)
//   fused kernel: per block = 64 edges, 256 threads
//     phase 1: h1 = relu(x@W1+b1); h2 = relu(h1@W2+b2)   (reg-tiled, W2 smem-staged)
//     phase 2: K = h2 @ W3p chunk-by-chunk (160 cols = 4 i-blocks), reg-tiled GEMM
//              with register-prefetch pipelined smem staging; chunk result -> smem,
//              then contract with [v;1] (+ b3) -> out[e, i]

typedef unsigned long long ull;

#define HID        128
#define CH         32
#define DOUT       1056          // 32*33
#define CPAD       40            // padded i-block width
#define WPAD       (CH * CPAD)   // 1280
#define TILE_E     64
#define NTHREADS   256
#define CHUNK      160           // 4 padded i-blocks per chunk
#define NCHUNK     8
#define KT_STRIDE  162
#define H1_STRIDE  130
#define E_TOTAL    262144

// padded + i-block-aligned copy of W3 (built each launch; deterministic)
__device__ float g_W3p[HID * WPAD];

__global__ void prep_w3_kernel(const float* __restrict__ W3) {
    int idx = blockIdx.x * blockDim.x + threadIdx.x;
    if (idx >= HID * WPAD) return;
    int h = idx / WPAD;
    int c = idx % WPAD;
    int i = c / CPAD, j = c % CPAD;
    g_W3p[idx] = (j < CH + 1) ? W3[h * DOUT + i * (CH + 1) + j] : 0.0f;
}

__device__ __forceinline__ ull fma2(ull a, ull b, ull c) {
    ull d;
    asm("fma.rn.f32x2 %0, %1, %2, %3;" : "=l"(d) : "l"(a), "l"(b), "l"(c));
    return d;
}
__device__ __forceinline__ ull pack2(float x, float y) {
    ull d;
    asm("mov.b64 %0, {%1, %2};" : "=l"(d) : "f"(x), "f"(y));
    return d;
}
__device__ __forceinline__ float2 unpack2(ull v) {
    float2 r;
    asm("mov.b64 {%0, %1}, %2;" : "=f"(r.x), "=f"(r.y) : "l"(v));
    return r;
}

__global__ __launch_bounds__(NTHREADS, 2)
void fnn_fused_kernel(const float* __restrict__ pos_i, const float* __restrict__ pos_j,
                      const float* __restrict__ v,
                      const float* __restrict__ W1, const float* __restrict__ b1,
                      const float* __restrict__ W2, const float* __restrict__ b2,
                      const float* __restrict__ b3,
                      float* __restrict__ out) {
    extern __shared__ float smem[];
    float* h2s = smem;                 // [64][128]   = 8192 f  (persistent)
    float* vs  = h2s + TILE_E * HID;   // [64][34]    = 2176 f  (persistent)
    float* ws  = vs + TILE_E * 34;     // [8][160]    = 1280 f  (stage buf; also xs)
    float* kt  = ws + 8 * CHUNK;       // [64][162]   = 10368 f (K chunk; also h1s[64][130])

    const int tid   = threadIdx.x;
    const int ebase = blockIdx.x * TILE_E;
    const int et = tid >> 4;           // 0..15 -> edge group
    const int ct = tid & 15;           // 0..15 -> column group (cols 2*ct + 32*p + {0,1})
    const int e0 = et * 4;

    // ---------------- stage inputs: x (pos_i|pos_j) into ws, v into vs -------------
    {
        int e = tid >> 2, comp = tid & 3;
        float val = (comp < 2) ? pos_i[(ebase + e) * 2 + comp]
                               : pos_j[(ebase + e) * 2 + (comp - 2)];
        ws[e * 4 + comp] = val;
    }
#pragma unroll
    for (int r = 0; r < 8; r++) {
        int idx = tid + NTHREADS * r;          // 0..2047
        int e = idx >> 5, j = idx & 31;
        vs[e * 34 + j] = v[(ebase + e) * CH + j];
    }
    __syncthreads();

    // ---------------- phase 1a: h1 = relu(x @ W1 + b1)  (into kt region) -----------
#pragma unroll 4
    for (int it = 0; it < 32; it++) {
        int idx = it * NTHREADS + tid;         // 0..8191
        int e = idx >> 7, o = idx & 127;
        const float* xe = ws + e * 4;
        float acc = __ldg(b1 + o);
        acc = fmaf(xe[0], __ldg(W1 + o),           acc);
        acc = fmaf(xe[1], __ldg(W1 + HID + o),     acc);
        acc = fmaf(xe[2], __ldg(W1 + 2 * HID + o), acc);
        acc = fmaf(xe[3], __ldg(W1 + 3 * HID + o), acc);
        kt[e * H1_STRIDE + o] = fmaxf(acc, 0.0f);
    }
    __syncthreads();

    // ---------------- phase 1b: h2 = relu(h1 @ W2 + b2) ----------------------------
    ull acc1[4][4];
#pragma unroll
    for (int s = 0; s < 4; s++)
#pragma unroll
        for (int p = 0; p < 4; p++) acc1[s][p] = 0ull;

    float rW2[4];
#pragma unroll
    for (int r = 0; r < 4; r++) rW2[r] = W2[tid + NTHREADS * r];   // k-tile 0

    for (int kt8 = 0; kt8 < 16; kt8++) {
        __syncthreads();                                  // prev tile reads done
#pragma unroll
        for (int r = 0; r < 4; r++) ws[tid + NTHREADS * r] = rW2[r];
        __syncthreads();
        if (kt8 < 15) {                                   // prefetch next tile
#pragma unroll
            for (int r = 0; r < 4; r++)
                rW2[r] = W2[(kt8 + 1) * 1024 + tid + NTHREADS * r];
        }
#pragma unroll
        for (int k = 0; k < 8; k++) {
            int hh = kt8 * 8 + k;
            float a0 = kt[(e0 + 0) * H1_STRIDE + hh];
            float a1 = kt[(e0 + 1) * H1_STRIDE + hh];
            float a2 = kt[(e0 + 2) * H1_STRIDE + hh];
            float a3 = kt[(e0 + 3) * H1_STRIDE + hh];
            ull pa0 = pack2(a0, a0), pa1 = pack2(a1, a1);
            ull pa2 = pack2(a2, a2), pa3 = pack2(a3, a3);
#pragma unroll
            for (int p = 0; p < 4; p++) {
                ull b = *(const ull*)(ws + k * HID + 2 * ct + 32 * p);
                acc1[0][p] = fma2(pa0, b, acc1[0][p]);
                acc1[1][p] = fma2(pa1, b, acc1[1][p]);
                acc1[2][p] = fma2(pa2, b, acc1[2][p]);
                acc1[3][p] = fma2(pa3, b, acc1[3][p]);
            }
        }
    }
    // epilogue: +b2, relu, store h2s
#pragma unroll
    for (int p = 0; p < 4; p++) {
        int o = 2 * ct + 32 * p;
        float bb0 = __ldg(b2 + o), bb1 = __ldg(b2 + o + 1);
#pragma unroll
        for (int s = 0; s < 4; s++) {
            float2 t = unpack2(acc1[s][p]);
            float2 rr = make_float2(fmaxf(t.x + bb0, 0.0f), fmaxf(t.y + bb1, 0.0f));
            *(float2*)(h2s + (e0 + s) * HID + o) = rr;
        }
    }

    // ---------------- phase 2: K = h2 @ W3p, chunked; contract with [v;1] ----------
    const int eC   = tid >> 2;     // contraction: one (edge, i) pair per thread/chunk
    const int iloc = tid & 3;

    float rW3[5];
#pragma unroll
    for (int r = 0; r < 5; r++) {                         // prefetch chunk0/ktile0
        int idx = tid + NTHREADS * r;
        int row = idx / CHUNK, col = idx % CHUNK;
        rW3[r] = g_W3p[row * WPAD + col];
    }

    for (int cc = 0; cc < NCHUNK; cc++) {
        ull acc2[4][5];
#pragma unroll
        for (int s = 0; s < 4; s++)
#pragma unroll
            for (int p = 0; p < 5; p++) acc2[s][p] = 0ull;

        for (int kt8 = 0; kt8 < 16; kt8++) {
            __syncthreads();                              // prev tile reads done
#pragma unroll
            for (int r = 0; r < 5; r++) ws[tid + NTHREADS * r] = rW3[r];
            __syncthreads();
            {                                             // prefetch next tile
                int nkt = kt8 + 1, ncc = cc;
                if (nkt == 16) { nkt = 0; ncc = cc + 1; }
                if (ncc < NCHUNK) {
#pragma unroll
                    for (int r = 0; r < 5; r++) {
                        int idx = tid + NTHREADS * r;
                        int row = idx / CHUNK, col = idx % CHUNK;
                        rW3[r] = g_W3p[(nkt * 8 + row) * WPAD + ncc * CHUNK + col];
                    }
                }
            }
#pragma unroll
            for (int k = 0; k < 8; k++) {
                int hh = kt8 * 8 + k;
                float a0 = h2s[(e0 + 0) * HID + hh];
                float a1 = h2s[(e0 + 1) * HID + hh];
                float a2 = h2s[(e0 + 2) * HID + hh];
                float a3 = h2s[(e0 + 3) * HID + hh];
                ull pa0 = pack2(a0, a0), pa1 = pack2(a1, a1);
                ull pa2 = pack2(a2, a2), pa3 = pack2(a3, a3);
#pragma unroll
                for (int p = 0; p < 5; p++) {
                    ull b = *(const ull*)(ws + k * CHUNK + 2 * ct + 32 * p);
                    acc2[0][p] = fma2(pa0, b, acc2[0][p]);
                    acc2[1][p] = fma2(pa1, b, acc2[1][p]);
                    acc2[2][p] = fma2(pa2, b, acc2[2][p]);
                    acc2[3][p] = fma2(pa3, b, acc2[3][p]);
                }
            }
        }
        __syncthreads();
        // dump K chunk to smem
#pragma unroll
        for (int s = 0; s < 4; s++)
#pragma unroll
            for (int p = 0; p < 5; p++) {
                float2 t = unpack2(acc2[s][p]);
                *(float2*)(kt + (e0 + s) * KT_STRIDE + 2 * ct + 32 * p) = t;
            }
        __syncthreads();
        // contraction: out[e, i] = sum_j (K[e,i,j] + b3[i,j]) * v[e,j]  +  (K[e,i,32] + b3[i,32])
        {
            int i = cc * 4 + iloc;
            const float* krow = kt + eC * KT_STRIDE + iloc * CPAD;
            const float* vrow = vs + eC * 34;
            const float* b3r  = b3 + i * (CH + 1);
            float acc = krow[CH] + __ldg(b3r + CH);
#pragma unroll
            for (int j = 0; j < CH; j++)
                acc = fmaf(krow[j] + __ldg(b3r + j), vrow[j], acc);
            out[(ebase + eC) * CH + i] = acc;
        }
    }
}

#define SMEM_BYTES ((TILE_E * HID + TILE_E * 34 + 8 * CHUNK + TILE_E * KT_STRIDE) * 4)  // 88064

extern "C" void kernel_launch(void* const* d_in, const int* in_sizes, int n_in,
                              void* d_out, int out_size) {
    const float* pos_i = (const float*)d_in[0];
    const float* pos_j = (const float*)d_in[1];
    const float* v     = (const float*)d_in[2];
    const float* W1    = (const float*)d_in[3];
    const float* b1    = (const float*)d_in[4];
    const float* W2    = (const float*)d_in[5];
    const float* b2    = (const float*)d_in[6];
    const float* W3    = (const float*)d_in[7];
    const float* b3    = (const float*)d_in[8];
    float* out = (float*)d_out;

    // build padded/aligned W3 copy (cheap; deterministic every call)
    prep_w3_kernel<<<(HID * WPAD + NTHREADS - 1) / NTHREADS, NTHREADS>>>(W3);

    // 88 KB dynamic smem > 48 KB default: opt in (idempotent, capture-safe)
    cudaFuncSetAttribute(fnn_fused_kernel,
                         cudaFuncAttributeMaxDynamicSharedMemorySize, SMEM_BYTES);

    fnn_fused_kernel<<<E_TOTAL / TILE_E, NTHREADS, SMEM_BYTES>>>(
        pos_i, pos_j, v, W1, b1, W2, b2, b3, out);
}

// round 7
// speedup vs baseline: 1.0011x; 1.0011x over previous
#include <cuda_runtime.h>

// FNNKernelTransform: per-edge MLP(4->128->128->1056) -> (32x33) kernel -> mat@v + bias
// Fused fp32 implementation with packed f32x2 FMA (Blackwell FFMA2).
//
// Strategy:
//   prep kernel : W3 [128,1056] -> W3p [128,1280] (each 33-col i-block zero-padded to 40)
//   fused kernel: per block = 64 edges, 256 threads
//     phase 1: h1 = relu(x@W1+b1); h2 = relu(h1@W2+b2)   (reg-tiled, W2 smem-staged)
//     phase 2: K = h2 @ W3p chunk-by-chunk (160 cols = 4 i-blocks), reg-tiled GEMM
//              with register-prefetch pipelined smem staging; chunk result -> smem,
//              then contract with [v;1] (+ b3) -> out[e, i]

typedef unsigned long long ull;

#define HID        128
#define CH         32
#define DOUT       1056          // 32*33
#define CPAD       40            // padded i-block width
#define WPAD       (CH * CPAD)   // 1280
#define TILE_E     64
#define NTHREADS   256
#define CHUNK      160           // 4 padded i-blocks per chunk
#define NCHUNK     8
#define KT_STRIDE  162
#define H1_STRIDE  130
#define E_TOTAL    262144

// padded + i-block-aligned copy of W3 (built each launch; deterministic)
__device__ float g_W3p[HID * WPAD];

__global__ void prep_w3_kernel(const float* __restrict__ W3) {
    int idx = blockIdx.x * blockDim.x + threadIdx.x;
    if (idx >= HID * WPAD) return;
    int h = idx / WPAD;
    int c = idx % WPAD;
    int i = c / CPAD, j = c % CPAD;
    g_W3p[idx] = (j < CH + 1) ? W3[h * DOUT + i * (CH + 1) + j] : 0.0f;
}

__device__ __forceinline__ ull fma2(ull a, ull b, ull c) {
    ull d;
    asm("fma.rn.f32x2 %0, %1, %2, %3;" : "=l"(d) : "l"(a), "l"(b), "l"(c));
    return d;
}
__device__ __forceinline__ ull pack2(float x, float y) {
    ull d;
    asm("mov.b64 %0, {%1, %2};" : "=l"(d) : "f"(x), "f"(y));
    return d;
}
__device__ __forceinline__ float2 unpack2(ull v) {
    float2 r;
    asm("mov.b64 {%0, %1}, %2;" : "=f"(r.x), "=f"(r.y) : "l"(v));
    return r;
}

__global__ __launch_bounds__(NTHREADS, 2)
void fnn_fused_kernel(const float* __restrict__ pos_i, const float* __restrict__ pos_j,
                      const float* __restrict__ v,
                      const float* __restrict__ W1, const float* __restrict__ b1,
                      const float* __restrict__ W2, const float* __restrict__ b2,
                      const float* __restrict__ b3,
                      float* __restrict__ out) {
    extern __shared__ float smem[];
    float* h2s = smem;                 // [64][128]   = 8192 f  (persistent)
    float* vs  = h2s + TILE_E * HID;   // [64][34]    = 2176 f  (persistent)
    float* ws  = vs + TILE_E * 34;     // [8][160]    = 1280 f  (stage buf; also xs)
    float* kt  = ws + 8 * CHUNK;       // [64][162]   = 10368 f (K chunk; also h1s[64][130])

    const int tid   = threadIdx.x;
    const int ebase = blockIdx.x * TILE_E;
    const int et = tid >> 4;           // 0..15 -> edge group
    const int ct = tid & 15;           // 0..15 -> column group (cols 2*ct + 32*p + {0,1})
    const int e0 = et * 4;

    // ---------------- stage inputs: x (pos_i|pos_j) into ws, v into vs -------------
    {
        int e = tid >> 2, comp = tid & 3;
        float val = (comp < 2) ? pos_i[(ebase + e) * 2 + comp]
                               : pos_j[(ebase + e) * 2 + (comp - 2)];
        ws[e * 4 + comp] = val;
    }
#pragma unroll
    for (int r = 0; r < 8; r++) {
        int idx = tid + NTHREADS * r;          // 0..2047
        int e = idx >> 5, j = idx & 31;
        vs[e * 34 + j] = v[(ebase + e) * CH + j];
    }
    __syncthreads();

    // ---------------- phase 1a: h1 = relu(x @ W1 + b1)  (into kt region) -----------
#pragma unroll 4
    for (int it = 0; it < 32; it++) {
        int idx = it * NTHREADS + tid;         // 0..8191
        int e = idx >> 7, o = idx & 127;
        const float* xe = ws + e * 4;
        float acc = __ldg(b1 + o);
        acc = fmaf(xe[0], __ldg(W1 + o),           acc);
        acc = fmaf(xe[1], __ldg(W1 + HID + o),     acc);
        acc = fmaf(xe[2], __ldg(W1 + 2 * HID + o), acc);
        acc = fmaf(xe[3], __ldg(W1 + 3 * HID + o), acc);
        kt[e * H1_STRIDE + o] = fmaxf(acc, 0.0f);
    }
    __syncthreads();

    // ---------------- phase 1b: h2 = relu(h1 @ W2 + b2) ----------------------------
    ull acc1[4][4];
#pragma unroll
    for (int s = 0; s < 4; s++)
#pragma unroll
        for (int p = 0; p < 4; p++) acc1[s][p] = 0ull;

    float rW2[4];
#pragma unroll
    for (int r = 0; r < 4; r++) rW2[r] = W2[tid + NTHREADS * r];   // k-tile 0

    for (int kt8 = 0; kt8 < 16; kt8++) {
        __syncthreads();                                  // prev tile reads done
#pragma unroll
        for (int r = 0; r < 4; r++) ws[tid + NTHREADS * r] = rW2[r];
        __syncthreads();
        if (kt8 < 15) {                                   // prefetch next tile
#pragma unroll
            for (int r = 0; r < 4; r++)
                rW2[r] = W2[(kt8 + 1) * 1024 + tid + NTHREADS * r];
        }
#pragma unroll
        for (int k = 0; k < 8; k++) {
            int hh = kt8 * 8 + k;
            float a0 = kt[(e0 + 0) * H1_STRIDE + hh];
            float a1 = kt[(e0 + 1) * H1_STRIDE + hh];
            float a2 = kt[(e0 + 2) * H1_STRIDE + hh];
            float a3 = kt[(e0 + 3) * H1_STRIDE + hh];
            ull pa0 = pack2(a0, a0), pa1 = pack2(a1, a1);
            ull pa2 = pack2(a2, a2), pa3 = pack2(a3, a3);
#pragma unroll
            for (int p = 0; p < 4; p++) {
                ull b = *(const ull*)(ws + k * HID + 2 * ct + 32 * p);
                acc1[0][p] = fma2(pa0, b, acc1[0][p]);
                acc1[1][p] = fma2(pa1, b, acc1[1][p]);
                acc1[2][p] = fma2(pa2, b, acc1[2][p]);
                acc1[3][p] = fma2(pa3, b, acc1[3][p]);
            }
        }
    }
    // epilogue: +b2, relu, store h2s
#pragma unroll
    for (int p = 0; p < 4; p++) {
        int o = 2 * ct + 32 * p;
        float bb0 = __ldg(b2 + o), bb1 = __ldg(b2 + o + 1);
#pragma unroll
        for (int s = 0; s < 4; s++) {
            float2 t = unpack2(acc1[s][p]);
            float2 rr = make_float2(fmaxf(t.x + bb0, 0.0f), fmaxf(t.y + bb1, 0.0f));
            *(float2*)(h2s + (e0 + s) * HID + o) = rr;
        }
    }

    // ---------------- phase 2: K = h2 @ W3p, chunked; contract with [v;1] ----------
    const int eC   = tid >> 2;     // contraction: one (edge, i) pair per thread/chunk
    const int iloc = tid & 3;

    float rW3[5];
#pragma unroll
    for (int r = 0; r < 5; r++) {                         // prefetch chunk0/ktile0
        int idx = tid + NTHREADS * r;
        int row = idx / CHUNK, col = idx % CHUNK;
        rW3[r] = g_W3p[row * WPAD + col];
    }

    for (int cc = 0; cc < NCHUNK; cc++) {
        ull acc2[4][5];
#pragma unroll
        for (int s = 0; s < 4; s++)
#pragma unroll
            for (int p = 0; p < 5; p++) acc2[s][p] = 0ull;

        for (int kt8 = 0; kt8 < 16; kt8++) {
            __syncthreads();                              // prev tile reads done
#pragma unroll
            for (int r = 0; r < 5; r++) ws[tid + NTHREADS * r] = rW3[r];
            __syncthreads();
            {                                             // prefetch next tile
                int nkt = kt8 + 1, ncc = cc;
                if (nkt == 16) { nkt = 0; ncc = cc + 1; }
                if (ncc < NCHUNK) {
#pragma unroll
                    for (int r = 0; r < 5; r++) {
                        int idx = tid + NTHREADS * r;
                        int row = idx / CHUNK, col = idx % CHUNK;
                        rW3[r] = g_W3p[(nkt * 8 + row) * WPAD + ncc * CHUNK + col];
                    }
                }
            }
#pragma unroll
            for (int k = 0; k < 8; k++) {
                int hh = kt8 * 8 + k;
                float a0 = h2s[(e0 + 0) * HID + hh];
                float a1 = h2s[(e0 + 1) * HID + hh];
                float a2 = h2s[(e0 + 2) * HID + hh];
                float a3 = h2s[(e0 + 3) * HID + hh];
                ull pa0 = pack2(a0, a0), pa1 = pack2(a1, a1);
                ull pa2 = pack2(a2, a2), pa3 = pack2(a3, a3);
#pragma unroll
                for (int p = 0; p < 5; p++) {
                    ull b = *(const ull*)(ws + k * CHUNK + 2 * ct + 32 * p);
                    acc2[0][p] = fma2(pa0, b, acc2[0][p]);
                    acc2[1][p] = fma2(pa1, b, acc2[1][p]);
                    acc2[2][p] = fma2(pa2, b, acc2[2][p]);
                    acc2[3][p] = fma2(pa3, b, acc2[3][p]);
                }
            }
        }
        __syncthreads();
        // dump K chunk to smem
#pragma unroll
        for (int s = 0; s < 4; s++)
#pragma unroll
            for (int p = 0; p < 5; p++) {
                float2 t = unpack2(acc2[s][p]);
                *(float2*)(kt + (e0 + s) * KT_STRIDE + 2 * ct + 32 * p) = t;
            }
        __syncthreads();
        // contraction: out[e, i] = sum_j (K[e,i,j] + b3[i,j]) * v[e,j]  +  (K[e,i,32] + b3[i,32])
        {
            int i = cc * 4 + iloc;
            const float* krow = kt + eC * KT_STRIDE + iloc * CPAD;
            const float* vrow = vs + eC * 34;
            const float* b3r  = b3 + i * (CH + 1);
            float acc = krow[CH] + __ldg(b3r + CH);
#pragma unroll
            for (int j = 0; j < CH; j++)
                acc = fmaf(krow[j] + __ldg(b3r + j), vrow[j], acc);
            out[(ebase + eC) * CH + i] = acc;
        }
    }
}

#define SMEM_BYTES ((TILE_E * HID + TILE_E * 34 + 8 * CHUNK + TILE_E * KT_STRIDE) * 4)  // 88064

extern "C" void kernel_launch(void* const* d_in, const int* in_sizes, int n_in,
                              void* d_out, int out_size) {
    const float* pos_i = (const float*)d_in[0];
    const float* pos_j = (const float*)d_in[1];
    const float* v     = (const float*)d_in[2];
    const float* W1    = (const float*)d_in[3];
    const float* b1    = (const float*)d_in[4];
    const float* W2    = (const float*)d_in[5];
    const float* b2    = (const float*)d_in[6];
    const float* W3    = (const float*)d_in[7];
    const float* b3    = (const float*)d_in[8];
    float* out = (float*)d_out;

    // build padded/aligned W3 copy (cheap; deterministic every call)
    prep_w3_kernel<<<(HID * WPAD + NTHREADS - 1) / NTHREADS, NTHREADS>>>(W3);

    // 88 KB dynamic smem > 48 KB default: opt in (idempotent, capture-safe)
    cudaFuncSetAttribute(fnn_fused_kernel,
                         cudaFuncAttributeMaxDynamicSharedMemorySize, SMEM_BYTES);

    fnn_fused_kernel<<<E_TOTAL / TILE_E, NTHREADS, SMEM_BYTES>>>(
        pos_i, pos_j, v, W1, b1, W2, b2, b3, out);
}